// round 6
// baseline (speedup 1.0000x reference)
#include <cuda_runtime.h>
#include <math.h>

#define NN   2048
#define TT   5
#define DD   64
#define KK   21
#define BB   32
#define ROWS (BB*NN)

// ---- scratch (device globals; no runtime allocation) ----
__device__ float g_cos[NN*NN];      // 16 MB
__device__ float g_ces[NN];         // emb . a_src[64:]
__device__ float g_ced[NN];         // emb . a_dst[64:]
__device__ float g_ws[TT];          // W^T a_src[:64]
__device__ float g_wd[TT];
__device__ float g_bs[2];           // Wb.a_src[:64], Wb.a_dst[:64]
__device__ int   g_idx[NN*KK];
__device__ float g_h[ROWS*DD];      // 16 MB
__device__ float g_esrc[ROWS];
__device__ float g_edst[ROWS];
__device__ float g_obuf[ROWS*DD];   // 16 MB
__device__ float g_part2[128*32];   // per agg block: 16 sums + 16 sumsqs
__device__ float g_mean[DD];
__device__ float g_inv[DD];

// monotonic float->uint key (total order matches float >)
__device__ __forceinline__ unsigned fkey(float f) {
    unsigned b = __float_as_uint(f);
    return (b & 0x80000000u) ? ~b : (b | 0x80000000u);
}

// packed f32x2 helpers (Blackwell): bit-exact per-lane fma, 2x issue density
__device__ __forceinline__ unsigned long long pk2(float lo, float hi) {
    unsigned long long r;
    asm("mov.b64 %0, {%1, %2};" : "=l"(r) : "f"(lo), "f"(hi));
    return r;
}
__device__ __forceinline__ void upk2(float& lo, float& hi, unsigned long long v) {
    asm("mov.b64 {%0, %1}, %2;" : "=f"(lo), "=f"(hi) : "l"(v));
}
__device__ __forceinline__ void ffma2(unsigned long long& d, unsigned long long a,
                                      unsigned long long b) {
    asm("fma.rn.f32x2 %0, %1, %2, %0;" : "+l"(d) : "l"(a), "l"(b));
}

// ---------------------------------------------------------------------------
// 1) pre: per-node emb-attention constants; warp 0 of block 0 also computes
//    the 5-dim projected attention weights.
__global__ __launch_bounds__(256) void pre_kernel(
    const float* __restrict__ emb, const float* __restrict__ W,
    const float* __restrict__ Wb,
    const float* __restrict__ a_src, const float* __restrict__ a_dst) {
    int t = threadIdx.x, lane = t & 31, w = t >> 5;
    int n = blockIdx.x * 8 + w;

    float e0 = emb[n * DD + lane], e1 = emb[n * DD + lane + 32];
    float ps = e0 * a_src[DD + lane] + e1 * a_src[DD + lane + 32];
    float pd = e0 * a_dst[DD + lane] + e1 * a_dst[DD + lane + 32];
    #pragma unroll
    for (int off = 16; off; off >>= 1) {
        ps += __shfl_down_sync(0xffffffffu, ps, off);
        pd += __shfl_down_sync(0xffffffffu, pd, off);
    }
    if (lane == 0) { g_ces[n] = ps; g_ced[n] = pd; }

    if (blockIdx.x == 0 && w == 0) {
        float a0 = a_src[lane], a1 = a_src[lane + 32];
        float d0 = a_dst[lane], d1 = a_dst[lane + 32];
        #pragma unroll
        for (int tt = 0; tt < TT; tt++) {
            float w0 = W[lane * TT + tt], w1 = W[(lane + 32) * TT + tt];
            float vs = w0 * a0 + w1 * a1;
            float vd = w0 * d0 + w1 * d1;
            #pragma unroll
            for (int off = 16; off; off >>= 1) {
                vs += __shfl_down_sync(0xffffffffu, vs, off);
                vd += __shfl_down_sync(0xffffffffu, vd, off);
            }
            if (lane == 0) { g_ws[tt] = vs; g_wd[tt] = vd; }
        }
        float b0 = Wb[lane], b1 = Wb[lane + 32];
        float vbs = b0 * a0 + b1 * a1;
        float vbd = b0 * d0 + b1 * d1;
        #pragma unroll
        for (int off = 16; off; off >>= 1) {
            vbs += __shfl_down_sync(0xffffffffu, vbs, off);
            vbd += __shfl_down_sync(0xffffffffu, vbd, off);
        }
        if (lane == 0) { g_bs[0] = vbs; g_bs[1] = vbd; }
    }
}

// ---------------------------------------------------------------------------
// 2) cos = (emb @ emb^T) / (norm_i*norm_j)   64x128 tile, f32x2 FMA
//    dynamic smem: As[64][64] | Bs[64][128] | nI[64] | nJ[128]  = 49,920 B
__global__ __launch_bounds__(256) void cos_kernel(const float* __restrict__ emb) {
    extern __shared__ float cs[];
    float* As = cs;              // [k][64]
    float* Bs = cs + 4096;       // [k][128]
    float* nI = cs + 12288;
    float* nJ = cs + 12352;
    int bi = blockIdx.y * 64;
    int bj = blockIdx.x * 128;
    int t  = threadIdx.x;
    int tx = t & 15, ty = t >> 4;

    #pragma unroll
    for (int u = 0; u < 4; u++) {
        int idx = t + u * 256;
        int row = idx >> 4, c4 = idx & 15;
        float4 a = *(const float4*)(emb + (bi + row) * DD + c4 * 4);
        As[(c4*4+0)*64+row] = a.x; As[(c4*4+1)*64+row] = a.y;
        As[(c4*4+2)*64+row] = a.z; As[(c4*4+3)*64+row] = a.w;
    }
    #pragma unroll
    for (int u = 0; u < 8; u++) {
        int idx = t + u * 256;
        int row = idx >> 4, c4 = idx & 15;
        float4 b = *(const float4*)(emb + (bj + row) * DD + c4 * 4);
        Bs[(c4*4+0)*128+row] = b.x; Bs[(c4*4+1)*128+row] = b.y;
        Bs[(c4*4+2)*128+row] = b.z; Bs[(c4*4+3)*128+row] = b.w;
    }
    if (t < 192) {
        int row = (t < 64) ? (bi + t) : (bj + t - 64);
        const float4* p = (const float4*)(emb + row * DD);
        float s = 0.f;
        #pragma unroll
        for (int q = 0; q < 16; q++) {
            float4 v = p[q];
            s += v.x*v.x + v.y*v.y + v.z*v.z + v.w*v.w;
        }
        if (t < 64) nI[t] = sqrtf(s); else nJ[t - 64] = sqrtf(s);
    }
    __syncthreads();

    unsigned long long acc[4][4];
    #pragma unroll
    for (int u = 0; u < 4; u++)
        #pragma unroll
        for (int v = 0; v < 4; v++) acc[u][v] = 0ull;

    #pragma unroll
    for (int k = 0; k < DD; k++) {
        float4 a4 = *(const float4*)&As[k * 64 + ty * 4];
        float4 b0 = *(const float4*)&Bs[k * 128 + tx * 8];
        float4 b1 = *(const float4*)&Bs[k * 128 + tx * 8 + 4];
        unsigned long long ap[4] = {pk2(a4.x, a4.x), pk2(a4.y, a4.y),
                                    pk2(a4.z, a4.z), pk2(a4.w, a4.w)};
        unsigned long long bp[4] = {pk2(b0.x, b0.y), pk2(b0.z, b0.w),
                                    pk2(b1.x, b1.y), pk2(b1.z, b1.w)};
        #pragma unroll
        for (int u = 0; u < 4; u++)
            #pragma unroll
            for (int v = 0; v < 4; v++) ffma2(acc[u][v], ap[u], bp[v]);
    }

    float njv[8];
    #pragma unroll
    for (int v = 0; v < 8; v++) njv[v] = nJ[tx * 8 + v];

    #pragma unroll
    for (int u = 0; u < 4; u++) {
        int i = bi + ty * 4 + u;
        float niv = nI[ty * 4 + u];
        float o[8];
        #pragma unroll
        for (int v = 0; v < 4; v++) upk2(o[2*v], o[2*v+1], acc[u][v]);
        float4 w0, w1;
        w0.x = o[0] / (niv * njv[0]); w0.y = o[1] / (niv * njv[1]);
        w0.z = o[2] / (niv * njv[2]); w0.w = o[3] / (niv * njv[3]);
        w1.x = o[4] / (niv * njv[4]); w1.y = o[5] / (niv * njv[5]);
        w1.z = o[6] / (niv * njv[6]); w1.w = o[7] / (niv * njv[7]);
        float4* dst = (float4*)(g_cos + (size_t)i * NN + bj + tx * 8);
        dst[0] = w0; dst[1] = w1;
    }
}

// ---------------------------------------------------------------------------
// 3) top-21: per-warp register-resident iterative argmax (redux-based),
//    then warp 0 merges 8x21 candidates. Tie-break: lower index first.
__global__ __launch_bounds__(256) void topk_kernel() {
    __shared__ unsigned cvs[8 * KK];
    __shared__ int      cis[8 * KK];
    int i = blockIdx.x;
    int t = threadIdx.x, lane = t & 31, w = t >> 5;

    int base = w * 256 + lane * 8;
    const float4* row4 = (const float4*)(g_cos + (size_t)i * NN);
    float4 aa = row4[(base >> 2)];
    float4 bb = row4[(base >> 2) + 1];
    float v[8] = {aa.x, aa.y, aa.z, aa.w, bb.x, bb.y, bb.z, bb.w};

    #pragma unroll 1
    for (int k = 0; k < KK; k++) {
        float bv = v[0]; int bq = 0;
        #pragma unroll
        for (int q = 1; q < 8; q++) if (v[q] > bv) { bv = v[q]; bq = q; }
        int bidx = base + bq;
        unsigned bk = fkey(bv);
        unsigned mk = __reduce_max_sync(0xffffffffu, bk);
        int cand = (bk == mk) ? bidx : 0x7fffffff;
        int widx = __reduce_min_sync(0xffffffffu, cand);
        if (lane == 0) { cvs[w * KK + k] = mk; cis[w * KK + k] = widx; }
        #pragma unroll
        for (int q = 0; q < 8; q++) if (widx == base + q) v[q] = -3e38f;
    }
    __syncthreads();

    if (w == 0) {
        unsigned kv[6]; int ki[6];
        #pragma unroll
        for (int q = 0; q < 6; q++) {
            int s = lane + 32 * q;
            if (s < 8 * KK) { kv[q] = cvs[s]; ki[q] = cis[s]; }
            else            { kv[q] = 0u;     ki[q] = 0x7fffffff; }
        }
        #pragma unroll 1
        for (int k = 0; k < KK; k++) {
            unsigned bkk = kv[0]; int bii = ki[0];
            #pragma unroll
            for (int q = 1; q < 6; q++) {
                if (kv[q] > bkk || (kv[q] == bkk && ki[q] < bii)) { bkk = kv[q]; bii = ki[q]; }
            }
            unsigned mk = __reduce_max_sync(0xffffffffu, bkk);
            int cand = (bkk == mk) ? bii : 0x7fffffff;
            int widx = __reduce_min_sync(0xffffffffu, cand);
            if (lane == 0) g_idx[i * KK + k] = widx;
            #pragma unroll
            for (int q = 0; q < 6; q++) if (ki[q] == widx) kv[q] = 0u;
        }
    }
}

// ---------------------------------------------------------------------------
// 4) h = x @ W^T + Wb (streamed), e_src/e_dst via 5-dim dots + per-node consts
__global__ __launch_bounds__(256) void h2_kernel(
    const float* __restrict__ x, const float* __restrict__ W,
    const float* __restrict__ Wb) {
    __shared__ float sW[DD * TT];
    __shared__ float sWb[DD];
    __shared__ float sx[32 * TT];
    int t = threadIdx.x;
    for (int q = t; q < DD * TT; q += 256) sW[q] = W[q];
    if (t < DD) sWb[t] = Wb[t];
    if (t < 32 * TT) sx[t] = x[blockIdx.x * 32 * TT + t];
    __syncthreads();

    int rl = t >> 3;
    int cg = (t & 7) * 8;
    int row = blockIdx.x * 32 + rl;

    float xv[TT];
    #pragma unroll
    for (int tt = 0; tt < TT; tt++) xv[tt] = sx[rl * TT + tt];

    float h[8];
    #pragma unroll
    for (int j = 0; j < 8; j++) {
        int c = cg + j;
        float acc = sWb[c];
        #pragma unroll
        for (int tt = 0; tt < TT; tt++) acc += xv[tt] * sW[c * TT + tt];
        h[j] = acc;
    }
    float4* hp = (float4*)(g_h + ((size_t)row << 6) + cg);
    hp[0] = make_float4(h[0], h[1], h[2], h[3]);
    hp[1] = make_float4(h[4], h[5], h[6], h[7]);

    if ((t & 7) == 0) {
        int n = row & (NN - 1);
        float es = g_bs[0], ed = g_bs[1];
        #pragma unroll
        for (int tt = 0; tt < TT; tt++) {
            es += xv[tt] * g_ws[tt];
            ed += xv[tt] * g_wd[tt];
        }
        g_esrc[row] = es + g_ces[n];
        g_edst[row] = ed + g_ced[n];
    }
}

// ---------------------------------------------------------------------------
// 5) agg: block = (batch b, channel-group cg of 16). Stage h[b,:,cg] slice in
//    smem (stride 20), inline softmax per 128-node tile, smem gather, fused
//    BN partial sums. Deterministic.
#define HSTR 20
#define S_H  0                        // 2048*20 floats
#define S_ED (2048*HSTR)              // 2048
#define S_AL (S_ED + 2048)            // 128*22
#define S_JI (S_AL + 128*22)          // 128*22 (ints)
#define S_RD (S_JI + 128*22)          // 512
#define AGG_SMEM ((S_RD + 512) * 4)   // bytes = 196,608

__global__ __launch_bounds__(256) void agg_kernel(const float* __restrict__ emb) {
    extern __shared__ float sm[];
    float* sh  = sm + S_H;
    float* sed = sm + S_ED;
    float* sal = sm + S_AL;
    int*   sji = (int*)(sm + S_JI);
    float* srd = sm + S_RD;

    int b  = blockIdx.x >> 2;
    int cg = blockIdx.x & 3;
    int t  = threadIdx.x;
    int rowbase = b << 11;

    // stage h channel slice + e_dst
    for (int idx = t; idx < 2048 * 4; idx += 256) {
        int row = idx >> 2, q = idx & 3;
        float4 v = *(const float4*)(g_h + (((size_t)(rowbase + row)) << 6) + cg * 16 + q * 4);
        *(float4*)(sh + row * HSTR + q * 4) = v;
    }
    for (int idx = t; idx < 2048; idx += 256) sed[idx] = g_edst[rowbase + idx];
    __syncthreads();

    int il = t >> 4;        // 0..15
    int c  = t & 15;
    int ch = cg * 16 + c;
    float accS = 0.f, accQ = 0.f;

    for (int tile = 0; tile < 16; tile++) {
        // phase A: alpha for 128 rows (threads 0..127)
        if (t < 128) {
            int i = tile * 128 + t;
            float es = g_esrc[rowbase + i];
            int   jj[KK];
            float ee[KK];
            float m = -3e38f;
            #pragma unroll
            for (int k = 0; k < KK; k++) {
                jj[k] = g_idx[i * KK + k];
                float v = es + sed[jj[k]];
                v = (v > 0.f) ? v : 0.2f * v;
                ee[k] = v;
                m = fmaxf(m, v);
            }
            float s = 0.f;
            #pragma unroll
            for (int k = 0; k < KK; k++) { ee[k] = __expf(ee[k] - m); s += ee[k]; }
            float rs = 1.f / s;
            #pragma unroll
            for (int k = 0; k < KK; k++) {
                sal[t * 22 + k] = ee[k] * rs;
                sji[t * 22 + k] = jj[k];
            }
        }
        __syncthreads();

        // phase B: gather (16 nodes x 16 ch per pass, 8 passes)
        #pragma unroll 1
        for (int p = 0; p < 8; p++) {
            int iloc = p * 16 + il;
            int i = tile * 128 + iloc;
            float z = 0.f;
            #pragma unroll
            for (int k = 0; k < KK; k++) {
                int   j  = sji[iloc * 22 + k];
                float al = sal[iloc * 22 + k];
                z += al * sh[j * HSTR + c];
            }
            float o = fmaxf(z, 0.f) * emb[i * DD + ch];
            g_obuf[(((size_t)(rowbase + i)) << 6) + ch] = o;
            accS += o;
            accQ += o * o;
        }
        __syncthreads();
    }

    // fused BN partials: reduce 256 threads -> 16 channels (deterministic)
    srd[t] = accS; srd[256 + t] = accQ;
    __syncthreads();
    if (t < 16) {
        float s = 0.f, q = 0.f;
        #pragma unroll
        for (int g = 0; g < 16; g++) {
            s += srd[t + 16 * g];
            q += srd[256 + t + 16 * g];
        }
        g_part2[blockIdx.x * 32 + t]      = s;
        g_part2[blockIdx.x * 32 + 16 + t] = q;
    }
}

// ---------------------------------------------------------------------------
// 6) finalize mean / rsqrt(var+eps)
__global__ void stats_kernel() {
    int ch = threadIdx.x;            // 64
    int cg = ch >> 4, c = ch & 15;
    float s = 0.f, q = 0.f;
    for (int b = 0; b < BB; b++) {
        int blk = (b << 2) + cg;
        s += g_part2[blk * 32 + c];
        q += g_part2[blk * 32 + 16 + c];
    }
    float mean = s / (float)ROWS;
    float var  = q / (float)ROWS - mean * mean;
    g_mean[ch] = mean;
    g_inv[ch]  = rsqrtf(var + 1e-5f);
}

// ---------------------------------------------------------------------------
// 7) BN apply + relu + fc  (warp per row, float2, channels 2l/2l+1)
__global__ __launch_bounds__(256) void out_kernel(
    const float* __restrict__ gamma, const float* __restrict__ beta,
    const float* __restrict__ fcw, const float* __restrict__ fcb,
    float* __restrict__ out) {
    int t = threadIdx.x, w = t >> 5, lane = t & 31;
    int row = blockIdx.x * 8 + w;
    float2 o  = *((const float2*)(g_obuf + ((size_t)row << 6)) + lane);
    float2 mn = *((const float2*)g_mean + lane);
    float2 iv = *((const float2*)g_inv + lane);
    float2 gm = *((const float2*)gamma + lane);
    float2 bt = *((const float2*)beta + lane);
    float2 fw = *((const float2*)fcw + lane);
    float v0 = fmaxf((o.x - mn.x) * iv.x * gm.x + bt.x, 0.f) * fw.x;
    float v1 = fmaxf((o.y - mn.y) * iv.y * gm.y + bt.y, 0.f) * fw.y;
    float acc = v0 + v1;
    #pragma unroll
    for (int off = 16; off; off >>= 1)
        acc += __shfl_down_sync(0xffffffffu, acc, off);
    if (lane == 0) out[row] = acc + fcb[0];
}

// ---------------------------------------------------------------------------
extern "C" void kernel_launch(void* const* d_in, const int* in_sizes, int n_in,
                              void* d_out, int out_size) {
    const float* x     = (const float*)d_in[0];
    const float* emb   = (const float*)d_in[1];
    const float* W     = (const float*)d_in[2];
    const float* Wb    = (const float*)d_in[3];
    const float* a_src = (const float*)d_in[4];
    const float* a_dst = (const float*)d_in[5];
    const float* gamma = (const float*)d_in[6];
    const float* beta  = (const float*)d_in[7];
    const float* fcw   = (const float*)d_in[8];
    const float* fcb   = (const float*)d_in[9];
    float* out = (float*)d_out;

    static int attr_done = 0;
    if (!attr_done) {
        cudaFuncSetAttribute(cos_kernel, cudaFuncAttributeMaxDynamicSharedMemorySize, 49920);
        cudaFuncSetAttribute(agg_kernel, cudaFuncAttributeMaxDynamicSharedMemorySize, AGG_SMEM);
        attr_done = 1;
    }

    pre_kernel<<<NN/8, 256>>>(emb, W, Wb, a_src, a_dst);
    cos_kernel<<<dim3(NN/128, NN/64), 256, 49920>>>(emb);
    topk_kernel<<<NN, 256>>>();
    h2_kernel<<<ROWS/32, 256>>>(x, W, Wb);
    agg_kernel<<<BB*4, 256, AGG_SMEM>>>(emb);
    stats_kernel<<<1, 64>>>();
    out_kernel<<<ROWS/8, 256>>>(gamma, beta, fcw, fcb, out);
}

// round 7
// speedup vs baseline: 1.2275x; 1.2275x over previous
#include <cuda_runtime.h>
#include <math.h>

#define NN   2048
#define TT   5
#define DD   64
#define KK   21
#define BB   32
#define ROWS (BB*NN)
#define RED_BLOCKS 128

// ---- scratch (device globals; no runtime allocation) ----
__device__ float g_cos[NN*NN];      // 16 MB
__device__ float g_norm[NN];
__device__ float g_ces[NN];         // emb . a_src[64:]
__device__ float g_ced[NN];         // emb . a_dst[64:]
__device__ float g_ws[TT];          // W^T a_src[:64]
__device__ float g_wd[TT];
__device__ float g_bs[2];           // Wb.a_src[:64], Wb.a_dst[:64]
__device__ int   g_idx[NN*KK];
__device__ float g_h[ROWS*DD];      // 16 MB
__device__ float g_esrc[ROWS];
__device__ float g_edst[ROWS];
__device__ float g_obuf[ROWS*DD];   // 16 MB
__device__ float g_part[RED_BLOCKS*128];
__device__ float g_mean[DD];
__device__ float g_inv[DD];

// monotonic float->uint key (total order matches float >)
__device__ __forceinline__ unsigned fkey(float f) {
    unsigned b = __float_as_uint(f);
    return (b & 0x80000000u) ? ~b : (b | 0x80000000u);
}

// packed f32x2 helpers (Blackwell): bit-exact per-lane fma, 2x issue density
__device__ __forceinline__ unsigned long long pk2(float lo, float hi) {
    unsigned long long r;
    asm("mov.b64 %0, {%1, %2};" : "=l"(r) : "f"(lo), "f"(hi));
    return r;
}
__device__ __forceinline__ void upk2(float& lo, float& hi, unsigned long long v) {
    asm("mov.b64 {%0, %1}, %2;" : "=f"(lo), "=f"(hi) : "l"(v));
}
__device__ __forceinline__ void ffma2(unsigned long long& d, unsigned long long a,
                                      unsigned long long b) {
    asm("fma.rn.f32x2 %0, %1, %2, %0;" : "+l"(d) : "l"(a), "l"(b));
}

// ---------------------------------------------------------------------------
// 1) pre: per-node norms + emb-attention constants; warp 0 of block 0 also
//    computes the 5-dim projected attention weights.
__global__ __launch_bounds__(256) void pre_kernel(
    const float* __restrict__ emb, const float* __restrict__ W,
    const float* __restrict__ Wb,
    const float* __restrict__ a_src, const float* __restrict__ a_dst) {
    int t = threadIdx.x, lane = t & 31, w = t >> 5;
    int n = blockIdx.x * 8 + w;

    float e0 = emb[n * DD + lane], e1 = emb[n * DD + lane + 32];
    float s  = e0 * e0 + e1 * e1;
    float ps = e0 * a_src[DD + lane] + e1 * a_src[DD + lane + 32];
    float pd = e0 * a_dst[DD + lane] + e1 * a_dst[DD + lane + 32];
    #pragma unroll
    for (int off = 16; off; off >>= 1) {
        s  += __shfl_down_sync(0xffffffffu, s, off);
        ps += __shfl_down_sync(0xffffffffu, ps, off);
        pd += __shfl_down_sync(0xffffffffu, pd, off);
    }
    if (lane == 0) {
        g_norm[n] = sqrtf(s);
        g_ces[n] = ps;
        g_ced[n] = pd;
    }

    if (blockIdx.x == 0 && w == 0) {
        float a0 = a_src[lane], a1 = a_src[lane + 32];
        float d0 = a_dst[lane], d1 = a_dst[lane + 32];
        #pragma unroll
        for (int tt = 0; tt < TT; tt++) {
            float w0 = W[lane * TT + tt], w1 = W[(lane + 32) * TT + tt];
            float vs = w0 * a0 + w1 * a1;
            float vd = w0 * d0 + w1 * d1;
            #pragma unroll
            for (int off = 16; off; off >>= 1) {
                vs += __shfl_down_sync(0xffffffffu, vs, off);
                vd += __shfl_down_sync(0xffffffffu, vd, off);
            }
            if (lane == 0) { g_ws[tt] = vs; g_wd[tt] = vd; }
        }
        float b0 = Wb[lane], b1 = Wb[lane + 32];
        float vbs = b0 * a0 + b1 * a1;
        float vbd = b0 * d0 + b1 * d1;
        #pragma unroll
        for (int off = 16; off; off >>= 1) {
            vbs += __shfl_down_sync(0xffffffffu, vbs, off);
            vbd += __shfl_down_sync(0xffffffffu, vbd, off);
        }
        if (lane == 0) { g_bs[0] = vbs; g_bs[1] = vbd; }
    }
}

// ---------------------------------------------------------------------------
// 2) cos = (emb @ emb^T) / (norm_i * norm_j)   64x64 tile, FFMA2 accumulation
//    (same smem layout as the 128us baseline; packed math is bit-exact)
__global__ __launch_bounds__(256) void cos_kernel(const float* __restrict__ emb) {
    __shared__ float As[DD][64];
    __shared__ float Bs[DD][64];
    int bi = blockIdx.y * 64;
    int bj = blockIdx.x * 64;
    int tx = threadIdx.x, ty = threadIdx.y;
    int t  = ty * 16 + tx;

    #pragma unroll
    for (int u = 0; u < 4; u++) {
        int idx = t + u * 256;
        int row = idx >> 4;
        int c4  = idx & 15;
        float4 a = *(const float4*)(emb + (bi + row) * DD + c4 * 4);
        As[c4*4+0][row] = a.x; As[c4*4+1][row] = a.y;
        As[c4*4+2][row] = a.z; As[c4*4+3][row] = a.w;
        float4 b = *(const float4*)(emb + (bj + row) * DD + c4 * 4);
        Bs[c4*4+0][row] = b.x; Bs[c4*4+1][row] = b.y;
        Bs[c4*4+2][row] = b.z; Bs[c4*4+3][row] = b.w;
    }
    __syncthreads();

    unsigned long long acc[4][2];
    #pragma unroll
    for (int u = 0; u < 4; u++) { acc[u][0] = 0ull; acc[u][1] = 0ull; }

    #pragma unroll
    for (int k = 0; k < DD; k++) {
        float4 a = *(const float4*)&As[k][ty * 4];
        float4 b = *(const float4*)&Bs[k][tx * 4];
        unsigned long long bp0 = pk2(b.x, b.y);
        unsigned long long bp1 = pk2(b.z, b.w);
        unsigned long long ap[4] = {pk2(a.x, a.x), pk2(a.y, a.y),
                                    pk2(a.z, a.z), pk2(a.w, a.w)};
        #pragma unroll
        for (int u = 0; u < 4; u++) {
            ffma2(acc[u][0], ap[u], bp0);
            ffma2(acc[u][1], ap[u], bp1);
        }
    }

    float ni[4], nj[4];
    #pragma unroll
    for (int u = 0; u < 4; u++) ni[u] = g_norm[bi + ty*4 + u];
    #pragma unroll
    for (int v = 0; v < 4; v++) nj[v] = g_norm[bj + tx*4 + v];

    #pragma unroll
    for (int u = 0; u < 4; u++) {
        int i = bi + ty*4 + u;
        float o[4];
        upk2(o[0], o[1], acc[u][0]);
        upk2(o[2], o[3], acc[u][1]);
        #pragma unroll
        for (int v = 0; v < 4; v++) {
            int j = bj + tx*4 + v;
            g_cos[(size_t)i * NN + j] = o[v] / (ni[u] * nj[v]);
        }
    }
}

// ---------------------------------------------------------------------------
// 3) top-21: per-warp register-resident iterative argmax (redux-based),
//    then warp 0 merges 8x21 candidates. Tie-break: lower index first.
__global__ __launch_bounds__(256) void topk_kernel() {
    __shared__ unsigned cvs[8 * KK];
    __shared__ int      cis[8 * KK];
    int i = blockIdx.x;
    int t = threadIdx.x, lane = t & 31, w = t >> 5;

    int base = w * 256 + lane * 8;
    const float4* row4 = (const float4*)(g_cos + (size_t)i * NN);
    float4 aa = row4[(base >> 2)];
    float4 bb = row4[(base >> 2) + 1];
    float v[8] = {aa.x, aa.y, aa.z, aa.w, bb.x, bb.y, bb.z, bb.w};

    #pragma unroll 1
    for (int k = 0; k < KK; k++) {
        float bv = v[0]; int bq = 0;
        #pragma unroll
        for (int q = 1; q < 8; q++) if (v[q] > bv) { bv = v[q]; bq = q; }
        int bidx = base + bq;
        unsigned bk = fkey(bv);
        unsigned mk = __reduce_max_sync(0xffffffffu, bk);
        int cand = (bk == mk) ? bidx : 0x7fffffff;
        int widx = __reduce_min_sync(0xffffffffu, cand);
        if (lane == 0) { cvs[w * KK + k] = mk; cis[w * KK + k] = widx; }
        #pragma unroll
        for (int q = 0; q < 8; q++) if (widx == base + q) v[q] = -3e38f;
    }
    __syncthreads();

    if (w == 0) {
        unsigned kv[6]; int ki[6];
        #pragma unroll
        for (int q = 0; q < 6; q++) {
            int s = lane + 32 * q;
            if (s < 8 * KK) { kv[q] = cvs[s]; ki[q] = cis[s]; }
            else            { kv[q] = 0u;     ki[q] = 0x7fffffff; }
        }
        #pragma unroll 1
        for (int k = 0; k < KK; k++) {
            unsigned bkk = kv[0]; int bii = ki[0];
            #pragma unroll
            for (int q = 1; q < 6; q++) {
                if (kv[q] > bkk || (kv[q] == bkk && ki[q] < bii)) { bkk = kv[q]; bii = ki[q]; }
            }
            unsigned mk = __reduce_max_sync(0xffffffffu, bkk);
            int cand = (bkk == mk) ? bii : 0x7fffffff;
            int widx = __reduce_min_sync(0xffffffffu, cand);
            if (lane == 0) g_idx[i * KK + k] = widx;
            #pragma unroll
            for (int q = 0; q < 6; q++) if (ki[q] == widx) kv[q] = 0u;
        }
    }
}

// ---------------------------------------------------------------------------
// 4) h = x @ W^T + Wb : persistent blocks (256 blocks x 256 thr), W staged
//    once, x via L1-broadcast LDG, e_src/e_dst via 5-dim dots.
__global__ __launch_bounds__(256) void h2_kernel(
    const float* __restrict__ x, const float* __restrict__ W,
    const float* __restrict__ Wb) {
    __shared__ float sW[DD * TT];
    __shared__ float sWb[DD];
    int t = threadIdx.x;
    for (int q = t; q < DD * TT; q += 256) sW[q] = W[q];
    if (t < DD) sWb[t] = Wb[t];
    __syncthreads();

    int rl = t >> 3;                 // local row 0..31
    int cg = (t & 7) * 8;            // channel group
    bool lead = (t & 7) == 0;

    #pragma unroll 1
    for (int g = 0; g < 8; g++) {
        int row = blockIdx.x * 256 + g * 32 + rl;
        const float* xp = x + (size_t)row * TT;
        float xv[TT];
        #pragma unroll
        for (int tt = 0; tt < TT; tt++) xv[tt] = __ldg(xp + tt);

        float h[8];
        #pragma unroll
        for (int j = 0; j < 8; j++) {
            int c = cg + j;
            float acc = sWb[c];
            #pragma unroll
            for (int tt = 0; tt < TT; tt++) acc += xv[tt] * sW[c * TT + tt];
            h[j] = acc;
        }
        float4* hp = (float4*)(g_h + ((size_t)row << 6) + cg);
        hp[0] = make_float4(h[0], h[1], h[2], h[3]);
        hp[1] = make_float4(h[4], h[5], h[6], h[7]);

        if (lead) {
            int n = row & (NN - 1);
            float es = g_bs[0], ed = g_bs[1];
            #pragma unroll
            for (int tt = 0; tt < TT; tt++) {
                es += xv[tt] * g_ws[tt];
                ed += xv[tt] * g_wd[tt];
            }
            g_esrc[row] = es + g_ces[n];
            g_edst[row] = ed + g_ced[n];
        }
    }
}

// ---------------------------------------------------------------------------
// 5) sparse attention + z*emb (channels 2*lane, 2*lane+1; float2 gathers)
__global__ __launch_bounds__(256) void agg_kernel(const float* __restrict__ emb) {
    int t = threadIdx.x, w = t >> 5, lane = t & 31;
    int row = blockIdx.x * 8 + w;
    int b = row >> 11;
    int i = row & (NN - 1);

    float es = g_esrc[row];
    float e = -3e38f; int j = 0;
    if (lane < KK) {
        j = g_idx[i * KK + lane];
        float v = es + g_edst[(b << 11) + j];
        e = (v > 0.f) ? v : 0.2f * v;
    }
    float m = e;
    #pragma unroll
    for (int off = 16; off; off >>= 1)
        m = fmaxf(m, __shfl_xor_sync(0xffffffffu, m, off));
    float wgt = (lane < KK) ? __expf(e - m) : 0.f;
    float s = wgt;
    #pragma unroll
    for (int off = 16; off; off >>= 1)
        s += __shfl_xor_sync(0xffffffffu, s, off);

    float z0 = 0.f, z1 = 0.f;
    #pragma unroll
    for (int k = 0; k < KK; k++) {
        float wk = __shfl_sync(0xffffffffu, wgt, k);
        int   jk = __shfl_sync(0xffffffffu, j, k);
        float2 hv = *((const float2*)(g_h + ((size_t)((b << 11) + jk) << 6)) + lane);
        z0 += wk * hv.x;
        z1 += wk * hv.y;
    }
    float rs = 1.f / s;
    z0 = fmaxf(z0 * rs, 0.f);
    z1 = fmaxf(z1 * rs, 0.f);
    float2 ev = *((const float2*)(emb + i * DD) + lane);
    float2 o = make_float2(z0 * ev.x, z1 * ev.y);
    *((float2*)(g_obuf + ((size_t)row << 6)) + lane) = o;
}

// ---------------------------------------------------------------------------
// 6) BN stats partial reduce (deterministic, float4)
__global__ __launch_bounds__(256) void red_kernel() {
    __shared__ float ss[1024], sq[1024];
    int t = threadIdx.x;
    int gt = blockIdx.x * 256 + t;
    const float4* p = (const float4*)g_obuf;
    float s[4] = {0.f, 0.f, 0.f, 0.f};
    float q[4] = {0.f, 0.f, 0.f, 0.f};
    const int total4 = ROWS * DD / 4;          // 1,048,576
    for (int idx = gt; idx < total4; idx += RED_BLOCKS * 256) {
        float4 v = p[idx];
        s[0] += v.x; q[0] += v.x * v.x;
        s[1] += v.y; q[1] += v.y * v.y;
        s[2] += v.z; q[2] += v.z * v.z;
        s[3] += v.w; q[3] += v.w * v.w;
    }
    #pragma unroll
    for (int jj = 0; jj < 4; jj++) { ss[t*4+jj] = s[jj]; sq[t*4+jj] = q[jj]; }
    __syncthreads();
    if (t < DD) {
        float a = 0.f, b2 = 0.f;
        #pragma unroll
        for (int k = 0; k < 16; k++) {
            int slot = t + 64 * k;
            a  += ss[slot];
            b2 += sq[slot];
        }
        g_part[blockIdx.x * 128 + t]      = a;
        g_part[blockIdx.x * 128 + 64 + t] = b2;
    }
}

// 7) finalize mean / rsqrt(var+eps)
__global__ void stats_kernel() {
    int c = threadIdx.x;  // 64
    float s = 0.f, s2 = 0.f;
    for (int bk = 0; bk < RED_BLOCKS; bk++) {
        s  += g_part[bk * 128 + c];
        s2 += g_part[bk * 128 + 64 + c];
    }
    float mean = s / (float)ROWS;
    float var  = s2 / (float)ROWS - mean * mean;
    g_mean[c] = mean;
    g_inv[c]  = rsqrtf(var + 1e-5f);
}

// ---------------------------------------------------------------------------
// 8) BN apply + relu + fc  (warp per row, float2, channels 2l/2l+1)
__global__ __launch_bounds__(256) void out_kernel(
    const float* __restrict__ gamma, const float* __restrict__ beta,
    const float* __restrict__ fcw, const float* __restrict__ fcb,
    float* __restrict__ out) {
    int t = threadIdx.x, w = t >> 5, lane = t & 31;
    int row = blockIdx.x * 8 + w;
    float2 o  = *((const float2*)(g_obuf + ((size_t)row << 6)) + lane);
    float2 mn = *((const float2*)g_mean + lane);
    float2 iv = *((const float2*)g_inv + lane);
    float2 gm = *((const float2*)gamma + lane);
    float2 bt = *((const float2*)beta + lane);
    float2 fw = *((const float2*)fcw + lane);
    float v0 = fmaxf((o.x - mn.x) * iv.x * gm.x + bt.x, 0.f) * fw.x;
    float v1 = fmaxf((o.y - mn.y) * iv.y * gm.y + bt.y, 0.f) * fw.y;
    float acc = v0 + v1;
    #pragma unroll
    for (int off = 16; off; off >>= 1)
        acc += __shfl_down_sync(0xffffffffu, acc, off);
    if (lane == 0) out[row] = acc + fcb[0];
}

// ---------------------------------------------------------------------------
extern "C" void kernel_launch(void* const* d_in, const int* in_sizes, int n_in,
                              void* d_out, int out_size) {
    const float* x     = (const float*)d_in[0];
    const float* emb   = (const float*)d_in[1];
    const float* W     = (const float*)d_in[2];
    const float* Wb    = (const float*)d_in[3];
    const float* a_src = (const float*)d_in[4];
    const float* a_dst = (const float*)d_in[5];
    const float* gamma = (const float*)d_in[6];
    const float* beta  = (const float*)d_in[7];
    const float* fcw   = (const float*)d_in[8];
    const float* fcb   = (const float*)d_in[9];
    float* out = (float*)d_out;

    pre_kernel<<<NN/8, 256>>>(emb, W, Wb, a_src, a_dst);
    cos_kernel<<<dim3(NN/64, NN/64), dim3(16, 16)>>>(emb);
    topk_kernel<<<NN, 256>>>();
    h2_kernel<<<ROWS/256, 256>>>(x, W, Wb);
    agg_kernel<<<ROWS/8, 256>>>(emb);
    red_kernel<<<RED_BLOCKS, 256>>>();
    stats_kernel<<<1, 64>>>();
    out_kernel<<<ROWS/8, 256>>>(gamma, beta, fcw, fcb, out);
}

// round 8
// speedup vs baseline: 1.4744x; 1.2011x over previous
#include <cuda_runtime.h>
#include <cuda_fp16.h>
#include <math.h>

#define NN   2048
#define TT   5
#define DD   64
#define KK   21
#define BB   32
#define ROWS (BB*NN)
#define RED_BLOCKS 128

// ---- scratch (device globals; no runtime allocation) ----
__device__ float  g_cos[NN*NN];      // 16 MB
__device__ float  g_norm[NN];
__device__ float  g_ces[NN];         // emb . a_src[64:]
__device__ float  g_ced[NN];         // emb . a_dst[64:]
__device__ float  g_ws[TT];          // W^T a_src[:64]
__device__ float  g_wd[TT];
__device__ float  g_bs[2];           // Wb.a_src[:64], Wb.a_dst[:64]
__device__ int    g_idx[NN*KK];
__device__ __half g_h[ROWS*DD];      // 8 MB (fp16; only consumer is agg gather)
__device__ float  g_esrc[ROWS];
__device__ float  g_edst[ROWS];
__device__ float  g_obuf[ROWS*DD];   // 16 MB
__device__ float  g_part[RED_BLOCKS*128];
__device__ float  g_mean[DD];
__device__ float  g_inv[DD];

// monotonic float->uint key (total order matches float >)
__device__ __forceinline__ unsigned fkey(float f) {
    unsigned b = __float_as_uint(f);
    return (b & 0x80000000u) ? ~b : (b | 0x80000000u);
}

// ---------------------------------------------------------------------------
// 1) pre: per-node norms + emb-attention constants; warp 0 of block 0 also
//    computes the 5-dim projected attention weights.
__global__ __launch_bounds__(256) void pre_kernel(
    const float* __restrict__ emb, const float* __restrict__ W,
    const float* __restrict__ Wb,
    const float* __restrict__ a_src, const float* __restrict__ a_dst) {
    int t = threadIdx.x, lane = t & 31, w = t >> 5;
    int n = blockIdx.x * 8 + w;

    float e0 = emb[n * DD + lane], e1 = emb[n * DD + lane + 32];
    float s  = e0 * e0 + e1 * e1;
    float ps = e0 * a_src[DD + lane] + e1 * a_src[DD + lane + 32];
    float pd = e0 * a_dst[DD + lane] + e1 * a_dst[DD + lane + 32];
    #pragma unroll
    for (int off = 16; off; off >>= 1) {
        s  += __shfl_down_sync(0xffffffffu, s, off);
        ps += __shfl_down_sync(0xffffffffu, ps, off);
        pd += __shfl_down_sync(0xffffffffu, pd, off);
    }
    if (lane == 0) {
        g_norm[n] = sqrtf(s);
        g_ces[n] = ps;
        g_ced[n] = pd;
    }

    if (blockIdx.x == 0 && w == 0) {
        float a0 = a_src[lane], a1 = a_src[lane + 32];
        float d0 = a_dst[lane], d1 = a_dst[lane + 32];
        #pragma unroll
        for (int tt = 0; tt < TT; tt++) {
            float w0 = W[lane * TT + tt], w1 = W[(lane + 32) * TT + tt];
            float vs = w0 * a0 + w1 * a1;
            float vd = w0 * d0 + w1 * d1;
            #pragma unroll
            for (int off = 16; off; off >>= 1) {
                vs += __shfl_down_sync(0xffffffffu, vs, off);
                vd += __shfl_down_sync(0xffffffffu, vd, off);
            }
            if (lane == 0) { g_ws[tt] = vs; g_wd[tt] = vd; }
        }
        float b0 = Wb[lane], b1 = Wb[lane + 32];
        float vbs = b0 * a0 + b1 * a1;
        float vbd = b0 * d0 + b1 * d1;
        #pragma unroll
        for (int off = 16; off; off >>= 1) {
            vbs += __shfl_down_sync(0xffffffffu, vbs, off);
            vbd += __shfl_down_sync(0xffffffffu, vbd, off);
        }
        if (lane == 0) { g_bs[0] = vbs; g_bs[1] = vbd; }
    }
}

// ---------------------------------------------------------------------------
// 2) cos = (emb @ emb^T) / (norm_i * norm_j)   64x64 tile, 4x4 per thread
//    (exact R5 version — known-good)
__global__ __launch_bounds__(256) void cos_kernel(const float* __restrict__ emb) {
    __shared__ float As[DD][64];
    __shared__ float Bs[DD][64];
    int bi = blockIdx.y * 64;
    int bj = blockIdx.x * 64;
    int tx = threadIdx.x, ty = threadIdx.y;
    int t  = ty * 16 + tx;

    #pragma unroll
    for (int u = 0; u < 4; u++) {
        int idx = t + u * 256;
        int row = idx >> 4;
        int c4  = idx & 15;
        float4 a = *(const float4*)(emb + (bi + row) * DD + c4 * 4);
        As[c4*4+0][row] = a.x; As[c4*4+1][row] = a.y;
        As[c4*4+2][row] = a.z; As[c4*4+3][row] = a.w;
        float4 b = *(const float4*)(emb + (bj + row) * DD + c4 * 4);
        Bs[c4*4+0][row] = b.x; Bs[c4*4+1][row] = b.y;
        Bs[c4*4+2][row] = b.z; Bs[c4*4+3][row] = b.w;
    }
    __syncthreads();

    float acc[4][4];
    #pragma unroll
    for (int u = 0; u < 4; u++)
        #pragma unroll
        for (int v = 0; v < 4; v++) acc[u][v] = 0.f;

    #pragma unroll
    for (int k = 0; k < DD; k++) {
        float4 a = *(const float4*)&As[k][ty * 4];
        float4 b = *(const float4*)&Bs[k][tx * 4];
        float ar[4] = {a.x, a.y, a.z, a.w};
        float br[4] = {b.x, b.y, b.z, b.w};
        #pragma unroll
        for (int u = 0; u < 4; u++)
            #pragma unroll
            for (int v = 0; v < 4; v++) acc[u][v] += ar[u] * br[v];
    }

    float ni[4], nj[4];
    #pragma unroll
    for (int u = 0; u < 4; u++) ni[u] = g_norm[bi + ty*4 + u];
    #pragma unroll
    for (int v = 0; v < 4; v++) nj[v] = g_norm[bj + tx*4 + v];

    #pragma unroll
    for (int u = 0; u < 4; u++) {
        int i = bi + ty*4 + u;
        #pragma unroll
        for (int v = 0; v < 4; v++) {
            int j = bj + tx*4 + v;
            g_cos[(size_t)i * NN + j] = acc[u][v] / (ni[u] * nj[v]);
        }
    }
}

// ---------------------------------------------------------------------------
// 3) top-21: per-lane sort-8 (Batcher, (key desc, idx asc)) into smem, then
//    21 pops via head pointers + redux. Warp0 merges 8 sorted 21-lists.
__global__ __launch_bounds__(256) void topk_kernel() {
    __shared__ unsigned sk[2048];
    __shared__ unsigned si[2048];
    __shared__ unsigned sck[8 * KK];
    __shared__ unsigned sci[8 * KK];
    int i = blockIdx.x;
    int t = threadIdx.x, lane = t & 31, w = t >> 5;
    int base = w * 256 + lane * 8;

    const float4* row4 = (const float4*)(g_cos + (size_t)i * NN);
    float4 aa = row4[base >> 2];
    float4 bb = row4[(base >> 2) + 1];
    float v[8] = {aa.x, aa.y, aa.z, aa.w, bb.x, bb.y, bb.z, bb.w};
    unsigned kk[8], ii[8];
    #pragma unroll
    for (int q = 0; q < 8; q++) { kk[q] = fkey(v[q]); ii[q] = base + q; }

    // Batcher 19-comparator network; "better" first = (key>, tie idx<)
#define CAS(a,b) { bool sw = (kk[a] < kk[b]) || (kk[a] == kk[b] && ii[a] > ii[b]); \
    unsigned k1 = sw ? kk[b] : kk[a], k2 = sw ? kk[a] : kk[b]; kk[a] = k1; kk[b] = k2; \
    unsigned i1 = sw ? ii[b] : ii[a], i2 = sw ? ii[a] : ii[b]; ii[a] = i1; ii[b] = i2; }
    CAS(0,1) CAS(2,3) CAS(4,5) CAS(6,7)
    CAS(0,2) CAS(1,3) CAS(4,6) CAS(5,7)
    CAS(1,2) CAS(5,6)
    CAS(0,4) CAS(1,5) CAS(2,6) CAS(3,7)
    CAS(2,4) CAS(3,5)
    CAS(1,2) CAS(3,4) CAS(5,6)
#undef CAS

    int sb = t * 8;
    #pragma unroll
    for (int q = 0; q < 8; q++) { sk[sb + q] = kk[q]; si[sb + q] = ii[q]; }
    // each thread reads only its own slots in phase 1: no sync needed

    int hp = 0;
    #pragma unroll 1
    for (int k = 0; k < KK; k++) {
        int hc = (hp < 8) ? hp : 7;
        unsigned kcur = sk[sb + hc];
        unsigned icur = si[sb + hc];
        if (hp >= 8) kcur = 0u;
        unsigned mk = __reduce_max_sync(0xffffffffu, kcur);
        unsigned cand = (kcur == mk) ? icur : 0xffffffffu;
        unsigned wi = __reduce_min_sync(0xffffffffu, cand);
        if (lane == 0) { sck[w * KK + k] = mk; sci[w * KK + k] = wi; }
        hp += (kcur == mk && icur == wi) ? 1 : 0;
    }
    __syncthreads();

    if (w == 0) {
        bool act = lane < 8;
        int hp2 = 0;
        #pragma unroll 1
        for (int k = 0; k < KK; k++) {
            int hc = (hp2 < KK) ? hp2 : KK - 1;
            unsigned kcur = act ? sck[lane * KK + hc] : 0u;
            unsigned icur = act ? sci[lane * KK + hc] : 0xffffffffu;
            if (hp2 >= KK) kcur = 0u;
            unsigned mk = __reduce_max_sync(0xffffffffu, kcur);
            unsigned cand = (kcur == mk) ? icur : 0xffffffffu;
            unsigned wi = __reduce_min_sync(0xffffffffu, cand);
            if (lane == 0) g_idx[i * KK + k] = (int)wi;
            hp2 += (kcur == mk && icur == wi) ? 1 : 0;
        }
    }
}

// ---------------------------------------------------------------------------
// 4) h = x @ W^T + Wb -> fp16; e_src/e_dst via 5-dim dots (fp32 exact).
//    Thread owns 4 channels; weights hoisted to registers; 8 rows per thread.
__global__ __launch_bounds__(256) void h2_kernel(
    const float* __restrict__ x, const float* __restrict__ W,
    const float* __restrict__ Wb) {
    __shared__ float sx[128 * TT];   // 640
    __shared__ float sW[DD * TT];    // 320
    __shared__ float sWb[DD];
    int t = threadIdx.x;
    for (int q = t; q < 128 * TT; q += 256) sx[q] = x[blockIdx.x * 128 * TT + q];
    for (int q = t; q < DD * TT; q += 256) sW[q] = W[q];
    if (t < DD) sWb[t] = Wb[t];
    __syncthreads();

    int cq = t & 15;        // channel quad: channels cq*4 .. cq*4+3
    int r0 = t >> 4;        // 0..15

    float wr[20], b4[4];
    #pragma unroll
    for (int j = 0; j < 4; j++) {
        #pragma unroll
        for (int tt = 0; tt < TT; tt++) wr[j * TT + tt] = sW[(cq * 4 + j) * TT + tt];
        b4[j] = sWb[cq * 4 + j];
    }
    float ws[TT], wd[TT];
    #pragma unroll
    for (int tt = 0; tt < TT; tt++) { ws[tt] = g_ws[tt]; wd[tt] = g_wd[tt]; }
    float bs0 = g_bs[0], bd0 = g_bs[1];

    #pragma unroll 1
    for (int g = 0; g < 8; g++) {
        int rl = g * 16 + r0;
        int row = blockIdx.x * 128 + rl;
        float xv[TT];
        #pragma unroll
        for (int tt = 0; tt < TT; tt++) xv[tt] = sx[rl * TT + tt];

        float h[4];
        #pragma unroll
        for (int j = 0; j < 4; j++) {
            float acc = b4[j];
            #pragma unroll
            for (int tt = 0; tt < TT; tt++) acc += xv[tt] * wr[j * TT + tt];
            h[j] = acc;
        }
        __half2 p0 = __floats2half2_rn(h[0], h[1]);
        __half2 p1 = __floats2half2_rn(h[2], h[3]);
        uint2 pk = make_uint2(*(unsigned*)&p0, *(unsigned*)&p1);
        *(uint2*)(g_h + ((size_t)row << 6) + cq * 4) = pk;

        if (cq == 0) {
            float es = bs0, ed = bd0;
            #pragma unroll
            for (int tt = 0; tt < TT; tt++) {
                es += xv[tt] * ws[tt];
                ed += xv[tt] * wd[tt];
            }
            int n = row & (NN - 1);
            g_esrc[row] = es + g_ces[n];
            g_edst[row] = ed + g_ced[n];
        }
    }
}

// ---------------------------------------------------------------------------
// 5) sparse attention + z*emb (channels 2*lane, 2*lane+1; half2 gathers)
__global__ __launch_bounds__(256) void agg_kernel(const float* __restrict__ emb) {
    int t = threadIdx.x, w = t >> 5, lane = t & 31;
    int row = blockIdx.x * 8 + w;
    int b = row >> 11;
    int i = row & (NN - 1);

    float es = g_esrc[row];
    float e = -3e38f; int j = 0;
    if (lane < KK) {
        j = g_idx[i * KK + lane];
        float v = es + g_edst[(b << 11) + j];
        e = (v > 0.f) ? v : 0.2f * v;
    }
    float m = e;
    #pragma unroll
    for (int off = 16; off; off >>= 1)
        m = fmaxf(m, __shfl_xor_sync(0xffffffffu, m, off));
    float wgt = (lane < KK) ? __expf(e - m) : 0.f;
    float s = wgt;
    #pragma unroll
    for (int off = 16; off; off >>= 1)
        s += __shfl_xor_sync(0xffffffffu, s, off);

    float z0 = 0.f, z1 = 0.f;
    #pragma unroll
    for (int k = 0; k < KK; k++) {
        float wk = __shfl_sync(0xffffffffu, wgt, k);
        int   jk = __shfl_sync(0xffffffffu, j, k);
        __half2 hh = *((const __half2*)(g_h + ((size_t)((b << 11) + jk) << 6)) + lane);
        float2 hv = __half22float2(hh);
        z0 += wk * hv.x;
        z1 += wk * hv.y;
    }
    float rs = 1.f / s;
    z0 = fmaxf(z0 * rs, 0.f);
    z1 = fmaxf(z1 * rs, 0.f);
    float2 ev = *((const float2*)(emb + i * DD) + lane);
    float2 o = make_float2(z0 * ev.x, z1 * ev.y);
    *((float2*)(g_obuf + ((size_t)row << 6)) + lane) = o;
}

// ---------------------------------------------------------------------------
// 6) BN stats partial reduce (deterministic, float4)
__global__ __launch_bounds__(256) void red_kernel() {
    __shared__ float ss[1024], sq[1024];
    int t = threadIdx.x;
    int gt = blockIdx.x * 256 + t;
    const float4* p = (const float4*)g_obuf;
    float s[4] = {0.f, 0.f, 0.f, 0.f};
    float q[4] = {0.f, 0.f, 0.f, 0.f};
    const int total4 = ROWS * DD / 4;
    for (int idx = gt; idx < total4; idx += RED_BLOCKS * 256) {
        float4 v = p[idx];
        s[0] += v.x; q[0] += v.x * v.x;
        s[1] += v.y; q[1] += v.y * v.y;
        s[2] += v.z; q[2] += v.z * v.z;
        s[3] += v.w; q[3] += v.w * v.w;
    }
    #pragma unroll
    for (int jj = 0; jj < 4; jj++) { ss[t*4+jj] = s[jj]; sq[t*4+jj] = q[jj]; }
    __syncthreads();
    if (t < DD) {
        float a = 0.f, b2 = 0.f;
        #pragma unroll
        for (int k = 0; k < 16; k++) {
            int slot = t + 64 * k;
            a  += ss[slot];
            b2 += sq[slot];
        }
        g_part[blockIdx.x * 128 + t]      = a;
        g_part[blockIdx.x * 128 + 64 + t] = b2;
    }
}

// 7) finalize mean / rsqrt(var+eps)
__global__ void stats_kernel() {
    int c = threadIdx.x;  // 64
    float s = 0.f, s2 = 0.f;
    for (int bk = 0; bk < RED_BLOCKS; bk++) {
        s  += g_part[bk * 128 + c];
        s2 += g_part[bk * 128 + 64 + c];
    }
    float mean = s / (float)ROWS;
    float var  = s2 / (float)ROWS - mean * mean;
    g_mean[c] = mean;
    g_inv[c]  = rsqrtf(var + 1e-5f);
}

// ---------------------------------------------------------------------------
// 8) BN apply + relu + fc  (warp per row, float2, channels 2l/2l+1)
__global__ __launch_bounds__(256) void out_kernel(
    const float* __restrict__ gamma, const float* __restrict__ beta,
    const float* __restrict__ fcw, const float* __restrict__ fcb,
    float* __restrict__ out) {
    int t = threadIdx.x, w = t >> 5, lane = t & 31;
    int row = blockIdx.x * 8 + w;
    float2 o  = *((const float2*)(g_obuf + ((size_t)row << 6)) + lane);
    float2 mn = *((const float2*)g_mean + lane);
    float2 iv = *((const float2*)g_inv + lane);
    float2 gm = *((const float2*)gamma + lane);
    float2 bt = *((const float2*)beta + lane);
    float2 fw = *((const float2*)fcw + lane);
    float v0 = fmaxf((o.x - mn.x) * iv.x * gm.x + bt.x, 0.f) * fw.x;
    float v1 = fmaxf((o.y - mn.y) * iv.y * gm.y + bt.y, 0.f) * fw.y;
    float acc = v0 + v1;
    #pragma unroll
    for (int off = 16; off; off >>= 1)
        acc += __shfl_down_sync(0xffffffffu, acc, off);
    if (lane == 0) out[row] = acc + fcb[0];
}

// ---------------------------------------------------------------------------
extern "C" void kernel_launch(void* const* d_in, const int* in_sizes, int n_in,
                              void* d_out, int out_size) {
    const float* x     = (const float*)d_in[0];
    const float* emb   = (const float*)d_in[1];
    const float* W     = (const float*)d_in[2];
    const float* Wb    = (const float*)d_in[3];
    const float* a_src = (const float*)d_in[4];
    const float* a_dst = (const float*)d_in[5];
    const float* gamma = (const float*)d_in[6];
    const float* beta  = (const float*)d_in[7];
    const float* fcw   = (const float*)d_in[8];
    const float* fcb   = (const float*)d_in[9];
    float* out = (float*)d_out;

    pre_kernel<<<NN/8, 256>>>(emb, W, Wb, a_src, a_dst);
    cos_kernel<<<dim3(NN/64, NN/64), dim3(16, 16)>>>(emb);
    topk_kernel<<<NN, 256>>>();
    h2_kernel<<<ROWS/128, 256>>>(x, W, Wb);
    agg_kernel<<<ROWS/8, 256>>>(emb);
    red_kernel<<<RED_BLOCKS, 256>>>();
    stats_kernel<<<1, 64>>>();
    out_kernel<<<ROWS/8, 256>>>(gamma, beta, fcw, fcb, out);
}